// round 9
// baseline (speedup 1.0000x reference)
#include <cuda_runtime.h>
#include <math_constants.h>

// ---------------- problem constants ----------------
#define B_ROWS 4096
#define S_DIM  544
#define H_DIM  256
#define D_DIM  128
#define M_KEYS 50000
#define TOPK   50
#define NSPLIT 8
#define CHUNK  (M_KEYS / NSPLIT)   // 6250
#define RB     64                  // rows per CTA in dist kernel
#define KT     128                 // keys per tile
#define DKS    16                  // d-slice for key staging
#define CB     32                  // candidate buffer per row
#define LN_EPS   1e-5f
#define DIST_EPS 1e-7f

// ---------------- scratch (device globals; no allocs allowed) ----------------
__device__ float g_h  [B_ROWS * H_DIM];
__device__ float g_v1 [B_ROWS * H_DIM];
__device__ float g_q  [B_ROWS * D_DIM];
__device__ float g_q2 [B_ROWS];
__device__ float g_net[B_ROWS];
__device__ float g_k2 [M_KEYS];
__device__ float g_cd [B_ROWS * NSPLIT * TOPK];
__device__ int   g_ci [B_ROWS * NSPLIT * TOPK];

// ---------------- f32x2 packed helpers (Blackwell) ----------------
__device__ __forceinline__ unsigned long long pack_dup(float x) {
    unsigned long long r;
    asm("mov.b64 %0, {%1, %1};" : "=l"(r) : "f"(x));
    return r;
}
__device__ __forceinline__ float2 unpack_f2(unsigned long long v) {
    float2 r;
    asm("mov.b64 {%0, %1}, %2;" : "=f"(r.x), "=f"(r.y) : "l"(v));
    return r;
}
__device__ __forceinline__ void ffma2(unsigned long long& d,
                                      unsigned long long a,
                                      unsigned long long b) {
    asm("fma.rn.f32x2 %0, %1, %2, %0;" : "+l"(d) : "l"(a), "l"(b));
}

// ---------------- kernel 1: ||k||^2 ----------------
__global__ void k2_kernel(const float* __restrict__ keys) {
    int warp = (blockIdx.x * blockDim.x + threadIdx.x) >> 5;
    int lane = threadIdx.x & 31;
    if (warp >= M_KEYS) return;
    float4 v = *reinterpret_cast<const float4*>(&keys[warp * D_DIM + lane * 4]);
    float s = v.x * v.x + v.y * v.y + v.z * v.z + v.w * v.w;
    #pragma unroll
    for (int o = 16; o; o >>= 1) s += __shfl_xor_sync(~0u, s, o);
    if (lane == 0) g_k2[warp] = s;
}

// ---------------- kernel 2: h = relu(X@W1+b1), v1 = relu(X@V1+c1) ----------------
// C[4096, 512] = X[4096,544] @ [W1 | V1], tiled 64x64, thread 4x4, f32x2 math.
__global__ __launch_bounds__(256) void enc1_kernel(
    const float* __restrict__ X,
    const float* __restrict__ W1, const float* __restrict__ b1,
    const float* __restrict__ V1, const float* __restrict__ c1) {
    __shared__ float Xs[8][68];   // 272B pitch: [ty*4] is 16B-aligned
    __shared__ float Ws[8][68];
    int i0 = blockIdx.x * 64;
    int j0 = blockIdx.y * 64;
    int tid = threadIdx.x;
    int ty = tid >> 4, tx = tid & 15;
    // acc[a][p] holds columns (p*2, p*2+1) of output row a (packed f32x2)
    unsigned long long acc[4][2];
    #pragma unroll
    for (int a = 0; a < 4; a++) { acc[a][0] = 0ull; acc[a][1] = 0ull; }

    for (int k0 = 0; k0 < S_DIM; k0 += 8) {
        {
            #pragma unroll
            for (int p = 0; p < 2; p++) {
                int e = tid + p * 256;
                int d = e & 7, i = e >> 3;
                Xs[d][i] = X[(i0 + i) * S_DIM + k0 + d];
            }
        }
        {
            #pragma unroll
            for (int p = 0; p < 2; p++) {
                int e = tid + p * 256;
                int j = e & 63, d = e >> 6;
                int jj = j0 + j;
                float w = (jj < H_DIM) ? W1[(k0 + d) * H_DIM + jj]
                                       : V1[(k0 + d) * H_DIM + (jj - H_DIM)];
                Ws[d][j] = w;
            }
        }
        __syncthreads();
        #pragma unroll
        for (int d = 0; d < 8; d++) {
            float4 xv = *reinterpret_cast<const float4*>(&Xs[d][ty * 4]);
            ulonglong2 wp = *reinterpret_cast<const ulonglong2*>(&Ws[d][tx * 4]);
            unsigned long long x0 = pack_dup(xv.x);
            unsigned long long x1 = pack_dup(xv.y);
            unsigned long long x2 = pack_dup(xv.z);
            unsigned long long x3 = pack_dup(xv.w);
            ffma2(acc[0][0], wp.x, x0); ffma2(acc[0][1], wp.y, x0);
            ffma2(acc[1][0], wp.x, x1); ffma2(acc[1][1], wp.y, x1);
            ffma2(acc[2][0], wp.x, x2); ffma2(acc[2][1], wp.y, x2);
            ffma2(acc[3][0], wp.x, x3); ffma2(acc[3][1], wp.y, x3);
        }
        __syncthreads();
    }
    #pragma unroll
    for (int a = 0; a < 4; a++) {
        int i = i0 + ty * 4 + a;
        float cv[4];
        {
            float2 p0 = unpack_f2(acc[a][0]);
            float2 p1 = unpack_f2(acc[a][1]);
            cv[0] = p0.x; cv[1] = p0.y; cv[2] = p1.x; cv[3] = p1.y;
        }
        #pragma unroll
        for (int b = 0; b < 4; b++) {
            int jj = j0 + tx * 4 + b;
            float bias = (jj < H_DIM) ? b1[jj] : c1[jj - H_DIM];
            float v = fmaxf(cv[b] + bias, 0.f);
            if (jj < H_DIM) g_h [i * H_DIM + jj]         = v;
            else            g_v1[i * H_DIM + jj - H_DIM] = v;
        }
    }
}

// ---------------- kernel 3: q = LN(h@W2+b2); v2 = relu(v1@V2+c2); net = v2@V3+c3 ----------------
__device__ __forceinline__ float block_sum_128(float v, float* sred, int tid) {
    #pragma unroll
    for (int o = 16; o; o >>= 1) v += __shfl_xor_sync(~0u, v, o);
    __syncthreads();
    if ((tid & 31) == 0) sred[tid >> 5] = v;
    __syncthreads();
    return sred[0] + sred[1] + sred[2] + sred[3];
}

__global__ __launch_bounds__(128) void enc2_kernel(
    const float* __restrict__ W2, const float* __restrict__ b2,
    const float* __restrict__ ln_g, const float* __restrict__ ln_b,
    const float* __restrict__ V2, const float* __restrict__ c2,
    const float* __restrict__ V3, const float* __restrict__ c3) {
    __shared__ float hs[8][H_DIM];
    __shared__ float vs[8][H_DIM];
    __shared__ float sred[4];
    int r0 = blockIdx.x * 8;
    int tid = threadIdx.x;   // 0..127 = output dim

    for (int e = tid; e < 8 * H_DIM / 4; e += 128) {
        int r = e >> 6;
        int c = (e & 63) * 4;
        *reinterpret_cast<float4*>(&hs[r][c]) =
            *reinterpret_cast<const float4*>(&g_h[(r0 + r) * H_DIM + c]);
        *reinterpret_cast<float4*>(&vs[r][c]) =
            *reinterpret_cast<const float4*>(&g_v1[(r0 + r) * H_DIM + c]);
    }
    __syncthreads();

    float accq[8], accv[8];
    float bq = b2[tid], bv = c2[tid];
    #pragma unroll
    for (int r = 0; r < 8; r++) { accq[r] = bq; accv[r] = bv; }

    for (int k = 0; k < H_DIM; k++) {
        float w2  = W2[k * D_DIM + tid];
        float v2w = V2[k * D_DIM + tid];
        #pragma unroll
        for (int r = 0; r < 8; r++) {
            accq[r] += hs[r][k] * w2;
            accv[r] += vs[r][k] * v2w;
        }
    }

    float g = ln_g[tid], bb = ln_b[tid], v3 = V3[tid], c3v = c3[0];
    for (int r = 0; r < 8; r++) {
        float x = accq[r];
        float mu = block_sum_128(x, sred, tid) * (1.f / 128.f);
        float dif = x - mu;
        float var = block_sum_128(dif * dif, sred, tid) * (1.f / 128.f);
        float qn = dif * rsqrtf(var + LN_EPS) * g + bb;
        g_q[(r0 + r) * D_DIM + tid] = qn;
        float q2 = block_sum_128(qn * qn, sred, tid);
        if (tid == 0) g_q2[r0 + r] = q2;
        float vv = fmaxf(accv[r], 0.f);
        float nv = block_sum_128(vv * v3, sred, tid);
        if (tid == 0) g_net[r0 + r] = nv + c3v;
    }
}

// ---------------- kernel 4: fused distance GEMM + per-chunk top-50 ----------------
struct __align__(16) DSmem {
    float qs[D_DIM][RB + 4];    // full q tile, staged ONCE (rows 272B: 16B-aligned)
    float ks[DKS][KT + 4];      // key d-slice (rows 528B: 16B-aligned)
    float k2s[KT];
    float q2s[RB];
    float thr[RB];
    int   cnt[RB];
    int   tcnt[RB];
    float tmax[RB];
    int   tmaxp[RB];
    float cdv[RB][CB];
    int   civ[RB][CB];
    float td[RB][TOPK];
    int   ti[RB][TOPK];
    int   s_overflow;
};

__device__ __forceinline__ void recompute_max(DSmem& sm, int lr, int lane) {
    float v = sm.td[lr][lane];
    int p = lane;
    if (lane < TOPK - 32) {
        float v2 = sm.td[lr][lane + 32];
        if (v2 > v) { v = v2; p = lane + 32; }
    }
    #pragma unroll
    for (int o = 16; o; o >>= 1) {
        float ov = __shfl_xor_sync(~0u, v, o);
        int   op = __shfl_xor_sync(~0u, p, o);
        if (ov > v) { v = ov; p = op; }
    }
    if (lane == 0) { sm.tmax[lr] = v; sm.tmaxp[lr] = p; }
    __syncwarp();
}

__global__ __launch_bounds__(256, 2) void dist_topk_kernel(const float* __restrict__ keys) {
    extern __shared__ char smem_raw[];
    DSmem& sm = *reinterpret_cast<DSmem*>(smem_raw);
    int tid = threadIdx.x;
    int r0 = blockIdx.x * RB;
    int split = blockIdx.y;
    int cstart = split * CHUNK;
    int cend = cstart + CHUNK;
    int tr = tid >> 4, tc = tid & 15;
    int lane = tid & 31, warp = tid >> 5;

    // per-thread fixed staging coordinates: e = tid + p*256 -> (m, dp)
    int st_m[2], st_dp[2];
    #pragma unroll
    for (int p = 0; p < 2; p++) {
        int e = tid + p * 256;
        st_m[p] = e >> 2;
        st_dp[p] = (e & 3) * 4;
    }

    for (int r = tid; r < RB; r += 256) {
        sm.q2s[r] = g_q2[r0 + r];
        sm.thr[r] = CUDART_INF_F;
        sm.cnt[r] = 0;
        sm.tcnt[r] = 0;
        sm.tmax[r] = -CUDART_INF_F;
        sm.tmaxp[r] = 0;
    }
    // stage the full q tile [64 rows x 128 d] once (transposed: qs[d][row])
    for (int e = tid; e < RB * (D_DIM / 4); e += 256) {
        int r = e >> 5;              // 0..63
        int dp = (e & 31) * 4;       // 0..124 step 4
        float4 v = *reinterpret_cast<const float4*>(&g_q[(r0 + r) * D_DIM + dp]);
        sm.qs[dp + 0][r] = v.x; sm.qs[dp + 1][r] = v.y;
        sm.qs[dp + 2][r] = v.z; sm.qs[dp + 3][r] = v.w;
    }
    __syncthreads();

    for (int m0 = cstart; m0 < cend; m0 += KT) {
        if (tid < KT) sm.k2s[tid] = g_k2[min(m0 + tid, M_KEYS - 1)];

        unsigned long long acc[4][4];
        #pragma unroll
        for (int a = 0; a < 4; a++)
            #pragma unroll
            for (int b = 0; b < 4; b++) acc[a][b] = 0ull;

        // ---- software-pipelined key staging + f32x2 microkernel ----
        float4 kreg[2];
        #pragma unroll
        for (int p = 0; p < 2; p++) {
            int mg = min(m0 + st_m[p], M_KEYS - 1);
            kreg[p] = *reinterpret_cast<const float4*>(&keys[mg * D_DIM + st_dp[p]]);
        }

        #pragma unroll 1
        for (int d0 = 0; d0 < D_DIM; d0 += DKS) {
            #pragma unroll
            for (int p = 0; p < 2; p++) {
                int m = st_m[p], dp = st_dp[p];
                sm.ks[dp + 0][m] = kreg[p].x; sm.ks[dp + 1][m] = kreg[p].y;
                sm.ks[dp + 2][m] = kreg[p].z; sm.ks[dp + 3][m] = kreg[p].w;
            }
            __syncthreads();
            if (d0 + DKS < D_DIM) {
                #pragma unroll
                for (int p = 0; p < 2; p++) {
                    int mg = min(m0 + st_m[p], M_KEYS - 1);
                    kreg[p] = *reinterpret_cast<const float4*>(
                        &keys[mg * D_DIM + d0 + DKS + st_dp[p]]);
                }
            }
            #pragma unroll
            for (int d = 0; d < DKS; d++) {
                float4 qv = *reinterpret_cast<const float4*>(&sm.qs[d0 + d][tr * 4]);
                ulonglong2 kA = *reinterpret_cast<const ulonglong2*>(&sm.ks[d][tc * 8]);
                ulonglong2 kB = *reinterpret_cast<const ulonglong2*>(&sm.ks[d][tc * 8 + 4]);
                unsigned long long q0 = pack_dup(qv.x);
                unsigned long long q1 = pack_dup(qv.y);
                unsigned long long q2 = pack_dup(qv.z);
                unsigned long long q3 = pack_dup(qv.w);
                ffma2(acc[0][0], kA.x, q0); ffma2(acc[0][1], kA.y, q0);
                ffma2(acc[0][2], kB.x, q0); ffma2(acc[0][3], kB.y, q0);
                ffma2(acc[1][0], kA.x, q1); ffma2(acc[1][1], kA.y, q1);
                ffma2(acc[1][2], kB.x, q1); ffma2(acc[1][3], kB.y, q1);
                ffma2(acc[2][0], kA.x, q2); ffma2(acc[2][1], kA.y, q2);
                ffma2(acc[2][2], kB.x, q2); ffma2(acc[2][3], kB.y, q2);
                ffma2(acc[3][0], kA.x, q3); ffma2(acc[3][1], kA.y, q3);
                ffma2(acc[3][2], kB.x, q3); ffma2(acc[3][3], kB.y, q3);
            }
            __syncthreads();
        }

        // ---- threshold-filtered push + exact merge (retry on overflow) ----
        unsigned done = 0;
        {
            int mbase = m0 + tc * 8;
            #pragma unroll
            for (int jj = 0; jj < 8; jj++)
                if (mbase + jj >= cend) done |= (0x01010101u << jj);
        }

        while (true) {
            if (tid == 0) sm.s_overflow = 0;
            __syncthreads();
            #pragma unroll
            for (int r = 0; r < 4; r++) {
                int lr = tr * 4 + r;
                float q2v = sm.q2s[lr];
                float t = sm.thr[lr];
                #pragma unroll
                for (int jp = 0; jp < 4; jp++) {
                    float2 dots = unpack_f2(acc[r][jp]);
                    #pragma unroll
                    for (int h = 0; h < 2; h++) {
                        int jj = jp * 2 + h;
                        int v = r * 8 + jj;
                        if (done & (1u << v)) continue;
                        float dot = h ? dots.y : dots.x;
                        int lm = tc * 8 + jj;
                        float dist = q2v + sm.k2s[lm] - 2.f * dot;
                        if (dist < t) {
                            int p = atomicAdd(&sm.cnt[lr], 1);
                            if (p < CB) {
                                sm.cdv[lr][p] = dist;
                                sm.civ[lr][p] = m0 + lm;
                                done |= (1u << v);
                            } else {
                                sm.s_overflow = 1;
                            }
                        } else {
                            done |= (1u << v);   // thr only decreases: safe to retire
                        }
                    }
                }
            }
            __syncthreads();
            // merge: warp w owns rows [w*8, w*8+8)
            for (int rr = 0; rr < 8; rr++) {
                int lr = warp * 8 + rr;
                int c = min(sm.cnt[lr], CB);
                for (int k = 0; k < c; k++) {
                    float dv = sm.cdv[lr][k];
                    int iv = sm.civ[lr][k];
                    int tc_ = sm.tcnt[lr];
                    if (tc_ < TOPK) {
                        if (lane == 0) {
                            sm.td[lr][tc_] = dv; sm.ti[lr][tc_] = iv;
                            sm.tcnt[lr] = tc_ + 1;
                        }
                        __syncwarp();
                        if (tc_ + 1 == TOPK) recompute_max(sm, lr, lane);
                    } else if (dv < sm.tmax[lr]) {
                        if (lane == 0) {
                            int mp = sm.tmaxp[lr];
                            sm.td[lr][mp] = dv; sm.ti[lr][mp] = iv;
                        }
                        __syncwarp();
                        recompute_max(sm, lr, lane);
                    }
                }
                if (lane == 0) {
                    sm.cnt[lr] = 0;
                    sm.thr[lr] = (sm.tcnt[lr] == TOPK) ? sm.tmax[lr] : CUDART_INF_F;
                }
            }
            __syncthreads();
            int of = sm.s_overflow;
            __syncthreads();
            if (!of) break;
        }
    }

    // write per-chunk top-50 indices (unsorted; distances kept for debug only)
    for (int rr = 0; rr < 8; rr++) {
        int lr = warp * 8 + rr;
        int gr = r0 + lr;
        for (int e = lane; e < TOPK; e += 32) {
            g_cd[(gr * NSPLIT + split) * TOPK + e] = sm.td[lr][e];
            g_ci[(gr * NSPLIT + split) * TOPK + e] = sm.ti[lr][e];
        }
    }
}

// ---------------- kernel 5: EXACT rescore of NSPLIT x 50 candidates -> top-50 -> output ----------------
// Rescores each candidate with Kahan-compensated fp32 + fp64 combine (error ~1e-12),
// rounds to the fp32 grid, and selects by lexicographic (distance, index) to mirror
// jax.lax.top_k's stable tie-breaking. This removes all my-side fp jitter from the
// selection boundary.
#define NC      (NSPLIT * TOPK)          // 400
#define NSLOT   ((NC + 31) / 32)         // 13

__global__ __launch_bounds__(128) void final_kernel(const float* __restrict__ keys,
                                                    const float* __restrict__ memv,
                                                    float* __restrict__ out) {
    __shared__ float qsh[4][D_DIM];
    int warp = threadIdx.x >> 5, lane = threadIdx.x & 31;
    int row = blockIdx.x * 4 + warp;
    const int* ci = &g_ci[row * NC];

    // stage this row's q into shared (warp-private slice)
    for (int i = lane; i < D_DIM / 4; i += 32)
        reinterpret_cast<float4*>(qsh[warp])[i] =
            reinterpret_cast<const float4*>(&g_q[row * D_DIM])[i];
    __syncwarp();

    float dv[NSLOT]; int iv[NSLOT];
    #pragma unroll 1
    for (int s = 0; s < NSLOT; s++) {
        int e = lane + s * 32;
        if (e < NC) {
            int idx = ci[e];
            const float4* kp = reinterpret_cast<const float4*>(&keys[idx * D_DIM]);
            const float4* qp = reinterpret_cast<const float4*>(qsh[warp]);
            float sum = 0.f, comp = 0.f;
            #pragma unroll 8
            for (int i = 0; i < D_DIM / 4; i++) {
                float4 kv = kp[i];
                float4 qv = qp[i];
                float df[4] = {qv.x - kv.x, qv.y - kv.y, qv.z - kv.z, qv.w - kv.w};
                #pragma unroll
                for (int j = 0; j < 4; j++) {
                    float p = df[j] * df[j];
                    float y = p - comp;
                    float t = sum + y;
                    comp = (t - sum) - y;
                    sum = t;
                }
            }
            double dd = (double)sum + (double)comp;   // near-exact squared distance
            dv[s] = (float)dd;                        // round to fp32 grid (like ref's d)
            iv[s] = idx;
        } else {
            dv[s] = CUDART_INF_F;
            iv[s] = 0x7FFFFFFF;
        }
    }

    // exact top-50 by (d, index) lexicographic, accumulate in ascending order
    float wsum = 0.f, wvsum = 0.f;
    for (int it = 0; it < TOPK; it++) {
        float bv = CUDART_INF_F; int bidx = 0x7FFFFFFF; int bs = 0;
        #pragma unroll
        for (int s = 0; s < NSLOT; s++) {
            if (dv[s] < bv || (dv[s] == bv && iv[s] < bidx)) {
                bv = dv[s]; bidx = iv[s]; bs = s;
            }
        }
        float v = bv; int vidx = bidx; int l = lane;
        #pragma unroll
        for (int o = 16; o; o >>= 1) {
            float ov = __shfl_xor_sync(~0u, v, o);
            int   oi = __shfl_xor_sync(~0u, vidx, o);
            int   ol = __shfl_xor_sync(~0u, l, o);
            if (ov < v || (ov == v && oi < vidx)) { v = ov; vidx = oi; l = ol; }
        }
        if (lane == l) { dv[bs] = CUDART_INF_F; iv[bs] = 0x7FFFFFFF; }
        float w = 1.f / (v + DIST_EPS);
        wsum += w;
        wvsum += w * memv[vidx];   // uniform address -> broadcast load
    }
    if (lane == 0)
        out[row] = 0.9f * (wvsum / wsum) + 0.1f * g_net[row];
}

// ---------------- launch ----------------
extern "C" void kernel_launch(void* const* d_in, const int* in_sizes, int n_in,
                              void* d_out, int out_size) {
    const float* states = (const float*)d_in[0];
    const float* W1 = (const float*)d_in[1];
    const float* b1 = (const float*)d_in[2];
    const float* W2 = (const float*)d_in[3];
    const float* b2 = (const float*)d_in[4];
    const float* ln_g = (const float*)d_in[5];
    const float* ln_b = (const float*)d_in[6];
    const float* keys = (const float*)d_in[7];
    const float* memv = (const float*)d_in[8];
    const float* V1 = (const float*)d_in[9];
    const float* c1 = (const float*)d_in[10];
    const float* V2 = (const float*)d_in[11];
    const float* c2 = (const float*)d_in[12];
    const float* V3 = (const float*)d_in[13];
    const float* c3 = (const float*)d_in[14];
    float* out = (float*)d_out;

    cudaFuncSetAttribute(dist_topk_kernel,
                         cudaFuncAttributeMaxDynamicSharedMemorySize,
                         (int)sizeof(DSmem));

    k2_kernel<<<(M_KEYS + 7) / 8, 256>>>(keys);
    dim3 g1(B_ROWS / 64, (H_DIM * 2) / 64);
    enc1_kernel<<<g1, 256>>>(states, W1, b1, V1, c1);
    enc2_kernel<<<B_ROWS / 8, 128>>>(W2, b2, ln_g, ln_b, V2, c2, V3, c3);
    dim3 g3(B_ROWS / RB, NSPLIT);
    dist_topk_kernel<<<g3, 256, sizeof(DSmem)>>>(keys);
    final_kernel<<<B_ROWS / 4, 128>>>(keys, memv, out);
}

// round 12
// speedup vs baseline: 1.2254x; 1.2254x over previous
#include <cuda_runtime.h>
#include <math_constants.h>

// ---------------- problem constants ----------------
#define B_ROWS 4096
#define S_DIM  544
#define H_DIM  256
#define D_DIM  128
#define M_KEYS 50000
#define TOPK   50
#define NSPLIT 8
#define CHUNK  (M_KEYS / NSPLIT)   // 6250
#define RB     64                  // rows per CTA in dist kernel
#define KT     128                 // keys per tile
#define DKS    32                  // d-slice for key staging
#define CB     32                  // candidate buffer per row
#define LN_EPS   1e-5f
#define DIST_EPS 1e-7f

// ---------------- scratch (device globals; no allocs allowed) ----------------
__device__ float g_h  [B_ROWS * H_DIM];
__device__ float g_v1 [B_ROWS * H_DIM];
__device__ float g_q  [B_ROWS * D_DIM];
__device__ float g_q2 [B_ROWS];
__device__ float g_net[B_ROWS];
__device__ float g_k2 [M_KEYS];
__device__ float g_cd [B_ROWS * NSPLIT * TOPK];
__device__ int   g_ci [B_ROWS * NSPLIT * TOPK];

// ---------------- f32x2 packed helpers (Blackwell) ----------------
__device__ __forceinline__ unsigned long long pack_dup(float x) {
    unsigned long long r;
    asm("mov.b64 %0, {%1, %1};" : "=l"(r) : "f"(x));
    return r;
}
__device__ __forceinline__ float2 unpack_f2(unsigned long long v) {
    float2 r;
    asm("mov.b64 {%0, %1}, %2;" : "=f"(r.x), "=f"(r.y) : "l"(v));
    return r;
}
__device__ __forceinline__ void ffma2(unsigned long long& d,
                                      unsigned long long a,
                                      unsigned long long b) {
    asm("fma.rn.f32x2 %0, %1, %2, %0;" : "+l"(d) : "l"(a), "l"(b));
}

// ---------------- kernel 1: ||k||^2 ----------------
__global__ void k2_kernel(const float* __restrict__ keys) {
    int warp = (blockIdx.x * blockDim.x + threadIdx.x) >> 5;
    int lane = threadIdx.x & 31;
    if (warp >= M_KEYS) return;
    float4 v = *reinterpret_cast<const float4*>(&keys[warp * D_DIM + lane * 4]);
    float s = v.x * v.x + v.y * v.y + v.z * v.z + v.w * v.w;
    #pragma unroll
    for (int o = 16; o; o >>= 1) s += __shfl_xor_sync(~0u, s, o);
    if (lane == 0) g_k2[warp] = s;
}

// ---------------- kernel 2: h = relu(X@W1+b1), v1 = relu(X@V1+c1) ----------------
__global__ __launch_bounds__(256) void enc1_kernel(
    const float* __restrict__ X,
    const float* __restrict__ W1, const float* __restrict__ b1,
    const float* __restrict__ V1, const float* __restrict__ c1) {
    __shared__ float Xs[8][68];
    __shared__ float Ws[8][68];
    int i0 = blockIdx.x * 64;
    int j0 = blockIdx.y * 64;
    int tid = threadIdx.x;
    int ty = tid >> 4, tx = tid & 15;
    unsigned long long acc[4][2];
    #pragma unroll
    for (int a = 0; a < 4; a++) { acc[a][0] = 0ull; acc[a][1] = 0ull; }

    for (int k0 = 0; k0 < S_DIM; k0 += 8) {
        {
            #pragma unroll
            for (int p = 0; p < 2; p++) {
                int e = tid + p * 256;
                int d = e & 7, i = e >> 3;
                Xs[d][i] = X[(i0 + i) * S_DIM + k0 + d];
            }
        }
        {
            #pragma unroll
            for (int p = 0; p < 2; p++) {
                int e = tid + p * 256;
                int j = e & 63, d = e >> 6;
                int jj = j0 + j;
                float w = (jj < H_DIM) ? W1[(k0 + d) * H_DIM + jj]
                                       : V1[(k0 + d) * H_DIM + (jj - H_DIM)];
                Ws[d][j] = w;
            }
        }
        __syncthreads();
        #pragma unroll
        for (int d = 0; d < 8; d++) {
            float4 xv = *reinterpret_cast<const float4*>(&Xs[d][ty * 4]);
            ulonglong2 wp = *reinterpret_cast<const ulonglong2*>(&Ws[d][tx * 4]);
            unsigned long long x0 = pack_dup(xv.x);
            unsigned long long x1 = pack_dup(xv.y);
            unsigned long long x2 = pack_dup(xv.z);
            unsigned long long x3 = pack_dup(xv.w);
            ffma2(acc[0][0], wp.x, x0); ffma2(acc[0][1], wp.y, x0);
            ffma2(acc[1][0], wp.x, x1); ffma2(acc[1][1], wp.y, x1);
            ffma2(acc[2][0], wp.x, x2); ffma2(acc[2][1], wp.y, x2);
            ffma2(acc[3][0], wp.x, x3); ffma2(acc[3][1], wp.y, x3);
        }
        __syncthreads();
    }
    #pragma unroll
    for (int a = 0; a < 4; a++) {
        int i = i0 + ty * 4 + a;
        float cv[4];
        {
            float2 p0 = unpack_f2(acc[a][0]);
            float2 p1 = unpack_f2(acc[a][1]);
            cv[0] = p0.x; cv[1] = p0.y; cv[2] = p1.x; cv[3] = p1.y;
        }
        #pragma unroll
        for (int b = 0; b < 4; b++) {
            int jj = j0 + tx * 4 + b;
            float bias = (jj < H_DIM) ? b1[jj] : c1[jj - H_DIM];
            float v = fmaxf(cv[b] + bias, 0.f);
            if (jj < H_DIM) g_h [i * H_DIM + jj]         = v;
            else            g_v1[i * H_DIM + jj - H_DIM] = v;
        }
    }
}

// ---------------- kernel 3: q = LN(h@W2+b2); v2 = relu(v1@V2+c2); net = v2@V3+c3 ----------------
__device__ __forceinline__ float block_sum_128(float v, float* sred, int tid) {
    #pragma unroll
    for (int o = 16; o; o >>= 1) v += __shfl_xor_sync(~0u, v, o);
    __syncthreads();
    if ((tid & 31) == 0) sred[tid >> 5] = v;
    __syncthreads();
    return sred[0] + sred[1] + sred[2] + sred[3];
}

__global__ __launch_bounds__(128) void enc2_kernel(
    const float* __restrict__ W2, const float* __restrict__ b2,
    const float* __restrict__ ln_g, const float* __restrict__ ln_b,
    const float* __restrict__ V2, const float* __restrict__ c2,
    const float* __restrict__ V3, const float* __restrict__ c3) {
    __shared__ float hs[8][H_DIM];
    __shared__ float vs[8][H_DIM];
    __shared__ float sred[4];
    int r0 = blockIdx.x * 8;
    int tid = threadIdx.x;   // 0..127 = output dim

    for (int e = tid; e < 8 * H_DIM / 4; e += 128) {
        int r = e >> 6;
        int c = (e & 63) * 4;
        *reinterpret_cast<float4*>(&hs[r][c]) =
            *reinterpret_cast<const float4*>(&g_h[(r0 + r) * H_DIM + c]);
        *reinterpret_cast<float4*>(&vs[r][c]) =
            *reinterpret_cast<const float4*>(&g_v1[(r0 + r) * H_DIM + c]);
    }
    __syncthreads();

    float accq[8], accv[8];
    float bq = b2[tid], bv = c2[tid];
    #pragma unroll
    for (int r = 0; r < 8; r++) { accq[r] = bq; accv[r] = bv; }

    for (int k = 0; k < H_DIM; k++) {
        float w2  = W2[k * D_DIM + tid];
        float v2w = V2[k * D_DIM + tid];
        #pragma unroll
        for (int r = 0; r < 8; r++) {
            accq[r] += hs[r][k] * w2;
            accv[r] += vs[r][k] * v2w;
        }
    }

    float g = ln_g[tid], bb = ln_b[tid], v3 = V3[tid], c3v = c3[0];
    for (int r = 0; r < 8; r++) {
        float x = accq[r];
        float mu = block_sum_128(x, sred, tid) * (1.f / 128.f);
        float dif = x - mu;
        float var = block_sum_128(dif * dif, sred, tid) * (1.f / 128.f);
        float qn = dif * rsqrtf(var + LN_EPS) * g + bb;
        g_q[(r0 + r) * D_DIM + tid] = qn;
        float q2 = block_sum_128(qn * qn, sred, tid);
        if (tid == 0) g_q2[r0 + r] = q2;
        float vv = fmaxf(accv[r], 0.f);
        float nv = block_sum_128(vv * v3, sred, tid);
        if (tid == 0) g_net[r0 + r] = nv + c3v;
    }
}

// ---------------- kernel 4: fused distance GEMM + per-chunk top-50 ----------------
// Crossbar-optimal map: lane -> 4 distinct keys (one fully-dense LDS.128),
// warp -> 8 rows (uniform-address broadcast q loads). acc[rp][kk] packs rows
// (2rp, 2rp+1) for key lane*4+kk.
struct __align__(16) DSmem {
    float qs[D_DIM][RB + 4];    // full q tile (row dim contiguous, 272B pitch)
    float ks[DKS][KT + 4];      // key d-slice (key dim contiguous, 528B pitch)
    float k2s[KT];
    float q2s[RB];
    float thr[RB];
    int   cnt[RB];
    int   tcnt[RB];
    float tmax[RB];
    int   tmaxp[RB];
    float cdv[RB][CB];
    int   civ[RB][CB];
    float td[RB][TOPK];
    int   ti[RB][TOPK];
    int   s_overflow;
};

__device__ __forceinline__ void recompute_max(DSmem& sm, int lr, int lane) {
    float v = sm.td[lr][lane];
    int p = lane;
    if (lane < TOPK - 32) {
        float v2 = sm.td[lr][lane + 32];
        if (v2 > v) { v = v2; p = lane + 32; }
    }
    #pragma unroll
    for (int o = 16; o; o >>= 1) {
        float ov = __shfl_xor_sync(~0u, v, o);
        int   op = __shfl_xor_sync(~0u, p, o);
        if (ov > v) { v = ov; p = op; }
    }
    if (lane == 0) { sm.tmax[lr] = v; sm.tmaxp[lr] = p; }
    __syncwarp();
}

__global__ __launch_bounds__(256, 2) void dist_topk_kernel(const float* __restrict__ keys) {
    extern __shared__ char smem_raw[];
    DSmem& sm = *reinterpret_cast<DSmem*>(smem_raw);
    int tid = threadIdx.x;
    int r0 = blockIdx.x * RB;
    int split = blockIdx.y;
    int cstart = split * CHUNK;
    int cend = cstart + CHUNK;
    int lane = tid & 31, warp = tid >> 5;

    for (int r = tid; r < RB; r += 256) {
        sm.q2s[r] = g_q2[r0 + r];
        sm.thr[r] = CUDART_INF_F;
        sm.cnt[r] = 0;
        sm.tcnt[r] = 0;
        sm.tmax[r] = -CUDART_INF_F;
        sm.tmaxp[r] = 0;
    }
    // stage the full q tile [64 rows x 128 d] once (transposed: qs[d][row])
    for (int e = tid; e < RB * (D_DIM / 4); e += 256) {
        int r = e >> 5;              // 0..63
        int dp = (e & 31) * 4;       // 0..124 step 4
        float4 v = *reinterpret_cast<const float4*>(&g_q[(r0 + r) * D_DIM + dp]);
        sm.qs[dp + 0][r] = v.x; sm.qs[dp + 1][r] = v.y;
        sm.qs[dp + 2][r] = v.z; sm.qs[dp + 3][r] = v.w;
    }
    __syncthreads();

    for (int m0 = cstart; m0 < cend; m0 += KT) {
        if (tid < KT) sm.k2s[tid] = g_k2[min(m0 + tid, M_KEYS - 1)];

        unsigned long long acc[4][4];   // [rowpair rp][key kk]
        #pragma unroll
        for (int a = 0; a < 4; a++)
            #pragma unroll
            for (int b = 0; b < 4; b++) acc[a][b] = 0ull;

        // ---- key staging (DKS=32 per slice) + f32x2 microkernel ----
        #pragma unroll 1
        for (int d0 = 0; d0 < D_DIM; d0 += DKS) {
            #pragma unroll
            for (int p = 0; p < 4; p++) {
                int e = tid + p * 256;         // 0..1023
                int m = e >> 3;                // 0..127 key
                int dp = (e & 7) * 4;          // 0..28 d-offset
                int mg = min(m0 + m, M_KEYS - 1);
                float4 v = *reinterpret_cast<const float4*>(
                    &keys[mg * D_DIM + d0 + dp]);
                sm.ks[dp + 0][m] = v.x; sm.ks[dp + 1][m] = v.y;
                sm.ks[dp + 2][m] = v.z; sm.ks[dp + 3][m] = v.w;
            }
            __syncthreads();
            #pragma unroll 8
            for (int d = 0; d < DKS; d++) {
                // q: rows warp*8..warp*8+7 (uniform address across warp -> broadcast)
                ulonglong2 qA = *reinterpret_cast<const ulonglong2*>(
                    &sm.qs[d0 + d][warp * 8]);
                ulonglong2 qB = *reinterpret_cast<const ulonglong2*>(
                    &sm.qs[d0 + d][warp * 8 + 4]);
                // keys: 4 distinct consecutive per lane (dense 512B across warp)
                float4 kv = *reinterpret_cast<const float4*>(&sm.ks[d][lane * 4]);
                unsigned long long k0 = pack_dup(kv.x);
                unsigned long long k1 = pack_dup(kv.y);
                unsigned long long k2 = pack_dup(kv.z);
                unsigned long long k3 = pack_dup(kv.w);
                ffma2(acc[0][0], qA.x, k0); ffma2(acc[0][1], qA.x, k1);
                ffma2(acc[0][2], qA.x, k2); ffma2(acc[0][3], qA.x, k3);
                ffma2(acc[1][0], qA.y, k0); ffma2(acc[1][1], qA.y, k1);
                ffma2(acc[1][2], qA.y, k2); ffma2(acc[1][3], qA.y, k3);
                ffma2(acc[2][0], qB.x, k0); ffma2(acc[2][1], qB.x, k1);
                ffma2(acc[2][2], qB.x, k2); ffma2(acc[2][3], qB.x, k3);
                ffma2(acc[3][0], qB.y, k0); ffma2(acc[3][1], qB.y, k1);
                ffma2(acc[3][2], qB.y, k2); ffma2(acc[3][3], qB.y, k3);
            }
            __syncthreads();
        }

        // ---- threshold-filtered push + exact merge (retry on overflow) ----
        // bit v = rowlocal*4 + kk  (rowlocal 0..7 within warp's rows, kk 0..3)
        unsigned done = 0;
        {
            int kbase = m0 + lane * 4;
            #pragma unroll
            for (int kk = 0; kk < 4; kk++)
                if (kbase + kk >= cend) done |= (0x11111111u << kk);
        }

        while (true) {
            if (tid == 0) sm.s_overflow = 0;
            __syncthreads();
            #pragma unroll
            for (int rp = 0; rp < 4; rp++) {
                #pragma unroll
                for (int h = 0; h < 2; h++) {
                    int rl = rp * 2 + h;
                    int lr = warp * 8 + rl;
                    float q2v = sm.q2s[lr];
                    float t = sm.thr[lr];
                    #pragma unroll
                    for (int kk = 0; kk < 4; kk++) {
                        int v = rl * 4 + kk;
                        if (done & (1u << v)) continue;
                        float2 dots = unpack_f2(acc[rp][kk]);
                        float dot = h ? dots.y : dots.x;
                        int lm = lane * 4 + kk;
                        float dist = q2v + sm.k2s[lm] - 2.f * dot;
                        if (dist < t) {
                            int p = atomicAdd(&sm.cnt[lr], 1);
                            if (p < CB) {
                                sm.cdv[lr][p] = dist;
                                sm.civ[lr][p] = m0 + lm;
                                done |= (1u << v);
                            } else {
                                sm.s_overflow = 1;
                            }
                        } else {
                            done |= (1u << v);   // thr only decreases: safe to retire
                        }
                    }
                }
            }
            __syncthreads();
            // merge: warp w owns rows [w*8, w*8+8)
            for (int rr = 0; rr < 8; rr++) {
                int lr = warp * 8 + rr;
                int c = min(sm.cnt[lr], CB);
                for (int k = 0; k < c; k++) {
                    float dv = sm.cdv[lr][k];
                    int iv = sm.civ[lr][k];
                    int tc_ = sm.tcnt[lr];
                    if (tc_ < TOPK) {
                        if (lane == 0) {
                            sm.td[lr][tc_] = dv; sm.ti[lr][tc_] = iv;
                            sm.tcnt[lr] = tc_ + 1;
                        }
                        __syncwarp();
                        if (tc_ + 1 == TOPK) recompute_max(sm, lr, lane);
                    } else if (dv < sm.tmax[lr]) {
                        if (lane == 0) {
                            int mp = sm.tmaxp[lr];
                            sm.td[lr][mp] = dv; sm.ti[lr][mp] = iv;
                        }
                        __syncwarp();
                        recompute_max(sm, lr, lane);
                    }
                }
                if (lane == 0) {
                    sm.cnt[lr] = 0;
                    sm.thr[lr] = (sm.tcnt[lr] == TOPK) ? sm.tmax[lr] : CUDART_INF_F;
                }
            }
            __syncthreads();
            int of = sm.s_overflow;
            __syncthreads();
            if (!of) break;
        }
    }

    // write per-chunk top-50 indices (unsorted)
    for (int rr = 0; rr < 8; rr++) {
        int lr = warp * 8 + rr;
        int gr = r0 + lr;
        for (int e = lane; e < TOPK; e += 32) {
            g_cd[(gr * NSPLIT + split) * TOPK + e] = sm.td[lr][e];
            g_ci[(gr * NSPLIT + split) * TOPK + e] = sm.ti[lr][e];
        }
    }
}

// ---------------- kernel 5: EXACT rescore of NSPLIT x 50 candidates -> top-50 -> output ----------------
#define NC      (NSPLIT * TOPK)          // 400
#define NSLOT   ((NC + 31) / 32)         // 13

__global__ __launch_bounds__(128) void final_kernel(const float* __restrict__ keys,
                                                    const float* __restrict__ memv,
                                                    float* __restrict__ out) {
    __shared__ float qsh[4][D_DIM];
    int warp = threadIdx.x >> 5, lane = threadIdx.x & 31;
    int row = blockIdx.x * 4 + warp;
    const int* ci = &g_ci[row * NC];

    for (int i = lane; i < D_DIM / 4; i += 32)
        reinterpret_cast<float4*>(qsh[warp])[i] =
            reinterpret_cast<const float4*>(&g_q[row * D_DIM])[i];
    __syncwarp();

    float dv[NSLOT]; int iv[NSLOT];
    #pragma unroll 1
    for (int s = 0; s < NSLOT; s++) {
        int e = lane + s * 32;
        if (e < NC) {
            int idx = ci[e];
            const float4* kp = reinterpret_cast<const float4*>(&keys[idx * D_DIM]);
            const float4* qp = reinterpret_cast<const float4*>(qsh[warp]);
            float sum = 0.f, comp = 0.f;
            #pragma unroll 8
            for (int i = 0; i < D_DIM / 4; i++) {
                float4 kv = kp[i];
                float4 qv = qp[i];
                float df[4] = {qv.x - kv.x, qv.y - kv.y, qv.z - kv.z, qv.w - kv.w};
                #pragma unroll
                for (int j = 0; j < 4; j++) {
                    float p = df[j] * df[j];
                    float y = p - comp;
                    float t = sum + y;
                    comp = (t - sum) - y;
                    sum = t;
                }
            }
            double dd = (double)sum + (double)comp;
            dv[s] = (float)dd;
            iv[s] = idx;
        } else {
            dv[s] = CUDART_INF_F;
            iv[s] = 0x7FFFFFFF;
        }
    }

    float wsum = 0.f, wvsum = 0.f;
    for (int it = 0; it < TOPK; it++) {
        float bv = CUDART_INF_F; int bidx = 0x7FFFFFFF; int bs = 0;
        #pragma unroll
        for (int s = 0; s < NSLOT; s++) {
            if (dv[s] < bv || (dv[s] == bv && iv[s] < bidx)) {
                bv = dv[s]; bidx = iv[s]; bs = s;
            }
        }
        float v = bv; int vidx = bidx; int l = lane;
        #pragma unroll
        for (int o = 16; o; o >>= 1) {
            float ov = __shfl_xor_sync(~0u, v, o);
            int   oi = __shfl_xor_sync(~0u, vidx, o);
            int   ol = __shfl_xor_sync(~0u, l, o);
            if (ov < v || (ov == v && oi < vidx)) { v = ov; vidx = oi; l = ol; }
        }
        if (lane == l) { dv[bs] = CUDART_INF_F; iv[bs] = 0x7FFFFFFF; }
        float w = 1.f / (v + DIST_EPS);
        wsum += w;
        wvsum += w * memv[vidx];
    }
    if (lane == 0)
        out[row] = 0.9f * (wvsum / wsum) + 0.1f * g_net[row];
}

// ---------------- launch ----------------
extern "C" void kernel_launch(void* const* d_in, const int* in_sizes, int n_in,
                              void* d_out, int out_size) {
    const float* states = (const float*)d_in[0];
    const float* W1 = (const float*)d_in[1];
    const float* b1 = (const float*)d_in[2];
    const float* W2 = (const float*)d_in[3];
    const float* b2 = (const float*)d_in[4];
    const float* ln_g = (const float*)d_in[5];
    const float* ln_b = (const float*)d_in[6];
    const float* keys = (const float*)d_in[7];
    const float* memv = (const float*)d_in[8];
    const float* V1 = (const float*)d_in[9];
    const float* c1 = (const float*)d_in[10];
    const float* V2 = (const float*)d_in[11];
    const float* c2 = (const float*)d_in[12];
    const float* V3 = (const float*)d_in[13];
    const float* c3 = (const float*)d_in[14];
    float* out = (float*)d_out;

    cudaFuncSetAttribute(dist_topk_kernel,
                         cudaFuncAttributeMaxDynamicSharedMemorySize,
                         (int)sizeof(DSmem));

    k2_kernel<<<(M_KEYS + 7) / 8, 256>>>(keys);
    dim3 g1(B_ROWS / 64, (H_DIM * 2) / 64);
    enc1_kernel<<<g1, 256>>>(states, W1, b1, V1, c1);
    enc2_kernel<<<B_ROWS / 8, 128>>>(W2, b2, ln_g, ln_b, V2, c2, V3, c3);
    dim3 g3(B_ROWS / RB, NSPLIT);
    dist_topk_kernel<<<g3, 256, sizeof(DSmem)>>>(keys);
    final_kernel<<<B_ROWS / 4, 128>>>(keys, memv, out);
}

// round 14
// speedup vs baseline: 1.2673x; 1.0342x over previous
#include <cuda_runtime.h>
#include <math_constants.h>
#include <cstdint>

// ---------------- problem constants ----------------
#define B_ROWS 4096
#define S_DIM  544
#define H_DIM  256
#define D_DIM  128
#define M_KEYS 50000
#define TOPK   50
#define NSPLIT 8
#define CHUNK  (M_KEYS / NSPLIT)   // 6250
#define RB     64                  // rows per CTA in dist kernel
#define KT     128                 // keys per tile
#define DKS    32                  // d-slice for key staging
#define NSLICE (D_DIM / DKS)       // 4
#define CB     32                  // candidate buffer per row
#define LN_EPS   1e-5f
#define DIST_EPS 1e-7f

// ---------------- scratch (device globals; no allocs allowed) ----------------
__device__ float g_h  [B_ROWS * H_DIM];
__device__ float g_v1 [B_ROWS * H_DIM];
__device__ float g_q  [B_ROWS * D_DIM];
__device__ float g_q2 [B_ROWS];
__device__ float g_net[B_ROWS];
__device__ float g_k2 [M_KEYS];
__device__ float g_cd [B_ROWS * NSPLIT * TOPK];
__device__ int   g_ci [B_ROWS * NSPLIT * TOPK];

// ---------------- f32x2 packed helpers (Blackwell) ----------------
__device__ __forceinline__ unsigned long long pack_dup(float x) {
    unsigned long long r;
    asm("mov.b64 %0, {%1, %1};" : "=l"(r) : "f"(x));
    return r;
}
__device__ __forceinline__ float2 unpack_f2(unsigned long long v) {
    float2 r;
    asm("mov.b64 {%0, %1}, %2;" : "=f"(r.x), "=f"(r.y) : "l"(v));
    return r;
}
__device__ __forceinline__ void ffma2(unsigned long long& d,
                                      unsigned long long a,
                                      unsigned long long b) {
    asm("fma.rn.f32x2 %0, %1, %2, %0;" : "+l"(d) : "l"(a), "l"(b));
}
__device__ __forceinline__ void cp_async16(unsigned int smem_dst, const void* gmem_src) {
    asm volatile("cp.async.cg.shared.global [%0], [%1], 16;"
                 :: "r"(smem_dst), "l"(gmem_src));
}
__device__ __forceinline__ void cp_async_commit() {
    asm volatile("cp.async.commit_group;");
}
template <int N>
__device__ __forceinline__ void cp_async_wait() {
    asm volatile("cp.async.wait_group %0;" :: "n"(N));
}

// ---------------- kernel 1: ||k||^2 ----------------
__global__ void k2_kernel(const float* __restrict__ keys) {
    int warp = (blockIdx.x * blockDim.x + threadIdx.x) >> 5;
    int lane = threadIdx.x & 31;
    if (warp >= M_KEYS) return;
    float4 v = *reinterpret_cast<const float4*>(&keys[warp * D_DIM + lane * 4]);
    float s = v.x * v.x + v.y * v.y + v.z * v.z + v.w * v.w;
    #pragma unroll
    for (int o = 16; o; o >>= 1) s += __shfl_xor_sync(~0u, s, o);
    if (lane == 0) g_k2[warp] = s;
}

// ---------------- kernel 2: h = relu(X@W1+b1), v1 = relu(X@V1+c1) ----------------
__global__ __launch_bounds__(256) void enc1_kernel(
    const float* __restrict__ X,
    const float* __restrict__ W1, const float* __restrict__ b1,
    const float* __restrict__ V1, const float* __restrict__ c1) {
    __shared__ float Xs[8][68];
    __shared__ float Ws[8][68];
    int i0 = blockIdx.x * 64;
    int j0 = blockIdx.y * 64;
    int tid = threadIdx.x;
    int ty = tid >> 4, tx = tid & 15;
    unsigned long long acc[4][2];
    #pragma unroll
    for (int a = 0; a < 4; a++) { acc[a][0] = 0ull; acc[a][1] = 0ull; }

    for (int k0 = 0; k0 < S_DIM; k0 += 8) {
        {
            #pragma unroll
            for (int p = 0; p < 2; p++) {
                int e = tid + p * 256;
                int d = e & 7, i = e >> 3;
                Xs[d][i] = X[(i0 + i) * S_DIM + k0 + d];
            }
        }
        {
            #pragma unroll
            for (int p = 0; p < 2; p++) {
                int e = tid + p * 256;
                int j = e & 63, d = e >> 6;
                int jj = j0 + j;
                float w = (jj < H_DIM) ? W1[(k0 + d) * H_DIM + jj]
                                       : V1[(k0 + d) * H_DIM + (jj - H_DIM)];
                Ws[d][j] = w;
            }
        }
        __syncthreads();
        #pragma unroll
        for (int d = 0; d < 8; d++) {
            float4 xv = *reinterpret_cast<const float4*>(&Xs[d][ty * 4]);
            ulonglong2 wp = *reinterpret_cast<const ulonglong2*>(&Ws[d][tx * 4]);
            unsigned long long x0 = pack_dup(xv.x);
            unsigned long long x1 = pack_dup(xv.y);
            unsigned long long x2 = pack_dup(xv.z);
            unsigned long long x3 = pack_dup(xv.w);
            ffma2(acc[0][0], wp.x, x0); ffma2(acc[0][1], wp.y, x0);
            ffma2(acc[1][0], wp.x, x1); ffma2(acc[1][1], wp.y, x1);
            ffma2(acc[2][0], wp.x, x2); ffma2(acc[2][1], wp.y, x2);
            ffma2(acc[3][0], wp.x, x3); ffma2(acc[3][1], wp.y, x3);
        }
        __syncthreads();
    }
    #pragma unroll
    for (int a = 0; a < 4; a++) {
        int i = i0 + ty * 4 + a;
        float cv[4];
        {
            float2 p0 = unpack_f2(acc[a][0]);
            float2 p1 = unpack_f2(acc[a][1]);
            cv[0] = p0.x; cv[1] = p0.y; cv[2] = p1.x; cv[3] = p1.y;
        }
        #pragma unroll
        for (int b = 0; b < 4; b++) {
            int jj = j0 + tx * 4 + b;
            float bias = (jj < H_DIM) ? b1[jj] : c1[jj - H_DIM];
            float v = fmaxf(cv[b] + bias, 0.f);
            if (jj < H_DIM) g_h [i * H_DIM + jj]         = v;
            else            g_v1[i * H_DIM + jj - H_DIM] = v;
        }
    }
}

// ---------------- kernel 3: q = LN(h@W2+b2); v2 = relu(v1@V2+c2); net = v2@V3+c3 ----------------
__device__ __forceinline__ float block_sum_128(float v, float* sred, int tid) {
    #pragma unroll
    for (int o = 16; o; o >>= 1) v += __shfl_xor_sync(~0u, v, o);
    __syncthreads();
    if ((tid & 31) == 0) sred[tid >> 5] = v;
    __syncthreads();
    return sred[0] + sred[1] + sred[2] + sred[3];
}

__global__ __launch_bounds__(128) void enc2_kernel(
    const float* __restrict__ W2, const float* __restrict__ b2,
    const float* __restrict__ ln_g, const float* __restrict__ ln_b,
    const float* __restrict__ V2, const float* __restrict__ c2,
    const float* __restrict__ V3, const float* __restrict__ c3) {
    __shared__ float hs[8][H_DIM];
    __shared__ float vs[8][H_DIM];
    __shared__ float sred[4];
    int r0 = blockIdx.x * 8;
    int tid = threadIdx.x;   // 0..127 = output dim

    for (int e = tid; e < 8 * H_DIM / 4; e += 128) {
        int r = e >> 6;
        int c = (e & 63) * 4;
        *reinterpret_cast<float4*>(&hs[r][c]) =
            *reinterpret_cast<const float4*>(&g_h[(r0 + r) * H_DIM + c]);
        *reinterpret_cast<float4*>(&vs[r][c]) =
            *reinterpret_cast<const float4*>(&g_v1[(r0 + r) * H_DIM + c]);
    }
    __syncthreads();

    float accq[8], accv[8];
    float bq = b2[tid], bv = c2[tid];
    #pragma unroll
    for (int r = 0; r < 8; r++) { accq[r] = bq; accv[r] = bv; }

    for (int k = 0; k < H_DIM; k++) {
        float w2  = W2[k * D_DIM + tid];
        float v2w = V2[k * D_DIM + tid];
        #pragma unroll
        for (int r = 0; r < 8; r++) {
            accq[r] += hs[r][k] * w2;
            accv[r] += vs[r][k] * v2w;
        }
    }

    float g = ln_g[tid], bb = ln_b[tid], v3 = V3[tid], c3v = c3[0];
    for (int r = 0; r < 8; r++) {
        float x = accq[r];
        float mu = block_sum_128(x, sred, tid) * (1.f / 128.f);
        float dif = x - mu;
        float var = block_sum_128(dif * dif, sred, tid) * (1.f / 128.f);
        float qn = dif * rsqrtf(var + LN_EPS) * g + bb;
        g_q[(r0 + r) * D_DIM + tid] = qn;
        float q2 = block_sum_128(qn * qn, sred, tid);
        if (tid == 0) g_q2[r0 + r] = q2;
        float vv = fmaxf(accv[r], 0.f);
        float nv = block_sum_128(vv * v3, sred, tid);
        if (tid == 0) g_net[r0 + r] = nv + c3v;
    }
}

// ---------------- kernel 4: fused distance GEMM + per-chunk top-50 ----------------
// Key smem: row-major XOR-swizzled ks[buf][m][d ^ ((m&7)<<2)], 128B rows.
// Staging: one cp.async(16B)/thread (4-wf floor). Compute: lane owns keys
// {lane, lane+32, lane+64, lane+96} so m&7 = lane&7 spans all swizzle groups
// (dense LDS.128, 4-wf floor). Double-buffered slices hide gmem latency.
struct __align__(16) DSmem {
    float qs[D_DIM][RB + 4];     // q tile, transposed (272B pitch)
    float ks[2][KT][DKS];        // swizzled key slices (128B rows)
    float k2s[KT];
    float q2s[RB];
    float thr[RB];
    int   cnt[RB];
    int   tcnt[RB];
    float tmax[RB];
    int   tmaxp[RB];
    float cdv[RB][CB];
    int   civ[RB][CB];
    float td[RB][TOPK];
    int   ti[RB][TOPK];
    int   s_overflow;
};

__device__ __forceinline__ void recompute_max(DSmem& sm, int lr, int lane) {
    float v = sm.td[lr][lane];
    int p = lane;
    if (lane < TOPK - 32) {
        float v2 = sm.td[lr][lane + 32];
        if (v2 > v) { v = v2; p = lane + 32; }
    }
    #pragma unroll
    for (int o = 16; o; o >>= 1) {
        float ov = __shfl_xor_sync(~0u, v, o);
        int   op = __shfl_xor_sync(~0u, p, o);
        if (ov > v) { v = ov; p = op; }
    }
    if (lane == 0) { sm.tmax[lr] = v; sm.tmaxp[lr] = p; }
    __syncwarp();
}

__global__ __launch_bounds__(256, 2) void dist_topk_kernel(const float* __restrict__ keys) {
    extern __shared__ char smem_raw[];
    DSmem& sm = *reinterpret_cast<DSmem*>(smem_raw);
    int tid = threadIdx.x;
    int r0 = blockIdx.x * RB;
    int split = blockIdx.y;
    int cstart = split * CHUNK;
    int cend = cstart + CHUNK;
    int lane = tid & 31, warp = tid >> 5;

    // fixed staging coords for this thread: e = tid + p*256
    int st_m[4], st_c[4], st_dp[4];
    #pragma unroll
    for (int p = 0; p < 4; p++) {
        int e = tid + p * 256;
        st_m[p] = e >> 3;                       // key 0..127
        st_dp[p] = (e & 7) * 4;                 // d-offset 0..28
        st_c[p] = st_dp[p] ^ ((st_m[p] & 7) << 2);  // swizzled column
    }

    for (int r = tid; r < RB; r += 256) {
        sm.q2s[r] = g_q2[r0 + r];
        sm.thr[r] = CUDART_INF_F;
        sm.cnt[r] = 0;
        sm.tcnt[r] = 0;
        sm.tmax[r] = -CUDART_INF_F;
        sm.tmaxp[r] = 0;
    }
    // stage the full q tile [64 rows x 128 d] once (transposed: qs[d][row])
    for (int e = tid; e < RB * (D_DIM / 4); e += 256) {
        int r = e >> 5;              // 0..63
        int dp = (e & 31) * 4;       // 0..124 step 4
        float4 v = *reinterpret_cast<const float4*>(&g_q[(r0 + r) * D_DIM + dp]);
        sm.qs[dp + 0][r] = v.x; sm.qs[dp + 1][r] = v.y;
        sm.qs[dp + 2][r] = v.z; sm.qs[dp + 3][r] = v.w;
    }
    __syncthreads();

    for (int m0 = cstart; m0 < cend; m0 += KT) {
        if (tid < KT) sm.k2s[tid] = g_k2[min(m0 + tid, M_KEYS - 1)];

        unsigned long long acc[4][4];   // [rowpair rp][key kk]
        #pragma unroll
        for (int a = 0; a < 4; a++)
            #pragma unroll
            for (int b = 0; b < 4; b++) acc[a][b] = 0ull;

        // prologue: stage slice 0 into buf 0
        #pragma unroll
        for (int p = 0; p < 4; p++) {
            int mg = min(m0 + st_m[p], M_KEYS - 1);
            cp_async16(
                (unsigned int)__cvta_generic_to_shared(&sm.ks[0][st_m[p]][st_c[p]]),
                &keys[mg * D_DIM + st_dp[p]]);
        }
        cp_async_commit();

        #pragma unroll
        for (int s = 0; s < NSLICE; s++) {
            int d0 = s * DKS;
            int buf = s & 1;
            if (s + 1 < NSLICE) {
                int nbuf = buf ^ 1;
                #pragma unroll
                for (int p = 0; p < 4; p++) {
                    int mg = min(m0 + st_m[p], M_KEYS - 1);
                    cp_async16(
                        (unsigned int)__cvta_generic_to_shared(&sm.ks[nbuf][st_m[p]][st_c[p]]),
                        &keys[mg * D_DIM + (s + 1) * DKS + st_dp[p]]);
                }
                cp_async_commit();
                cp_async_wait<1>();   // slice s complete; slice s+1 in flight
            } else {
                cp_async_wait<0>();
            }
            __syncthreads();

            int csw = (lane & 7) << 2;   // this lane's swizzle offset
            #pragma unroll
            for (int dc = 0; dc < DKS; dc += 4) {
                float4 kv[4];
                #pragma unroll
                for (int kk = 0; kk < 4; kk++) {
                    kv[kk] = *reinterpret_cast<const float4*>(
                        &sm.ks[buf][kk * 32 + lane][dc ^ csw]);
                }
                #pragma unroll
                for (int dd = 0; dd < 4; dd++) {
                    ulonglong2 qA = *reinterpret_cast<const ulonglong2*>(
                        &sm.qs[d0 + dc + dd][warp * 8]);
                    ulonglong2 qB = *reinterpret_cast<const ulonglong2*>(
                        &sm.qs[d0 + dc + dd][warp * 8 + 4]);
                    unsigned long long k0 = pack_dup(reinterpret_cast<const float*>(&kv[0])[dd]);
                    unsigned long long k1 = pack_dup(reinterpret_cast<const float*>(&kv[1])[dd]);
                    unsigned long long k2 = pack_dup(reinterpret_cast<const float*>(&kv[2])[dd]);
                    unsigned long long k3 = pack_dup(reinterpret_cast<const float*>(&kv[3])[dd]);
                    ffma2(acc[0][0], qA.x, k0); ffma2(acc[0][1], qA.x, k1);
                    ffma2(acc[0][2], qA.x, k2); ffma2(acc[0][3], qA.x, k3);
                    ffma2(acc[1][0], qA.y, k0); ffma2(acc[1][1], qA.y, k1);
                    ffma2(acc[1][2], qA.y, k2); ffma2(acc[1][3], qA.y, k3);
                    ffma2(acc[2][0], qB.x, k0); ffma2(acc[2][1], qB.x, k1);
                    ffma2(acc[2][2], qB.x, k2); ffma2(acc[2][3], qB.x, k3);
                    ffma2(acc[3][0], qB.y, k0); ffma2(acc[3][1], qB.y, k1);
                    ffma2(acc[3][2], qB.y, k2); ffma2(acc[3][3], qB.y, k3);
                }
            }
            __syncthreads();
        }

        // ---- threshold-filtered push + exact merge (retry on overflow) ----
        // bit v = rowlocal*4 + kk; this lane's key kk -> index kk*32 + lane
        unsigned done = 0;
        #pragma unroll
        for (int kk = 0; kk < 4; kk++)
            if (m0 + kk * 32 + lane >= cend) done |= (0x11111111u << kk);

        while (true) {
            if (tid == 0) sm.s_overflow = 0;
            __syncthreads();
            #pragma unroll
            for (int rp = 0; rp < 4; rp++) {
                #pragma unroll
                for (int h = 0; h < 2; h++) {
                    int rl = rp * 2 + h;
                    int lr = warp * 8 + rl;
                    float q2v = sm.q2s[lr];
                    float t = sm.thr[lr];
                    #pragma unroll
                    for (int kk = 0; kk < 4; kk++) {
                        int v = rl * 4 + kk;
                        if (done & (1u << v)) continue;
                        float2 dots = unpack_f2(acc[rp][kk]);
                        float dot = h ? dots.y : dots.x;
                        int lm = kk * 32 + lane;
                        float dist = q2v + sm.k2s[lm] - 2.f * dot;
                        if (dist < t) {
                            int p = atomicAdd(&sm.cnt[lr], 1);
                            if (p < CB) {
                                sm.cdv[lr][p] = dist;
                                sm.civ[lr][p] = m0 + lm;
                                done |= (1u << v);
                            } else {
                                sm.s_overflow = 1;
                            }
                        } else {
                            done |= (1u << v);   // thr only decreases: safe to retire
                        }
                    }
                }
            }
            __syncthreads();
            // merge: warp w owns rows [w*8, w*8+8)
            for (int rr = 0; rr < 8; rr++) {
                int lr = warp * 8 + rr;
                int c = min(sm.cnt[lr], CB);
                for (int k = 0; k < c; k++) {
                    float dv = sm.cdv[lr][k];
                    int iv = sm.civ[lr][k];
                    int tc_ = sm.tcnt[lr];
                    if (tc_ < TOPK) {
                        if (lane == 0) {
                            sm.td[lr][tc_] = dv; sm.ti[lr][tc_] = iv;
                            sm.tcnt[lr] = tc_ + 1;
                        }
                        __syncwarp();
                        if (tc_ + 1 == TOPK) recompute_max(sm, lr, lane);
                    } else if (dv < sm.tmax[lr]) {
                        if (lane == 0) {
                            int mp = sm.tmaxp[lr];
                            sm.td[lr][mp] = dv; sm.ti[lr][mp] = iv;
                        }
                        __syncwarp();
                        recompute_max(sm, lr, lane);
                    }
                }
                if (lane == 0) {
                    sm.cnt[lr] = 0;
                    sm.thr[lr] = (sm.tcnt[lr] == TOPK) ? sm.tmax[lr] : CUDART_INF_F;
                }
            }
            __syncthreads();
            int of = sm.s_overflow;
            __syncthreads();
            if (!of) break;
        }
    }

    // write per-chunk top-50 indices (unsorted)
    for (int rr = 0; rr < 8; rr++) {
        int lr = warp * 8 + rr;
        int gr = r0 + lr;
        for (int e = lane; e < TOPK; e += 32) {
            g_cd[(gr * NSPLIT + split) * TOPK + e] = sm.td[lr][e];
            g_ci[(gr * NSPLIT + split) * TOPK + e] = sm.ti[lr][e];
        }
    }
}

// ---------------- kernel 5: EXACT rescore of NSPLIT x 50 candidates -> top-50 -> output ----------------
#define NC      (NSPLIT * TOPK)          // 400
#define NSLOT   ((NC + 31) / 32)         // 13

__global__ __launch_bounds__(128) void final_kernel(const float* __restrict__ keys,
                                                    const float* __restrict__ memv,
                                                    float* __restrict__ out) {
    __shared__ float qsh[4][D_DIM];
    int warp = threadIdx.x >> 5, lane = threadIdx.x & 31;
    int row = blockIdx.x * 4 + warp;
    const int* ci = &g_ci[row * NC];

    for (int i = lane; i < D_DIM / 4; i += 32)
        reinterpret_cast<float4*>(qsh[warp])[i] =
            reinterpret_cast<const float4*>(&g_q[row * D_DIM])[i];
    __syncwarp();

    float dv[NSLOT]; int iv[NSLOT];
    #pragma unroll 1
    for (int s = 0; s < NSLOT; s++) {
        int e = lane + s * 32;
        if (e < NC) {
            int idx = ci[e];
            const float4* kp = reinterpret_cast<const float4*>(&keys[idx * D_DIM]);
            const float4* qp = reinterpret_cast<const float4*>(qsh[warp]);
            float sum = 0.f, comp = 0.f;
            #pragma unroll 8
            for (int i = 0; i < D_DIM / 4; i++) {
                float4 kv = kp[i];
                float4 qv = qp[i];
                float df[4] = {qv.x - kv.x, qv.y - kv.y, qv.z - kv.z, qv.w - kv.w};
                #pragma unroll
                for (int j = 0; j < 4; j++) {
                    float p = df[j] * df[j];
                    float y = p - comp;
                    float t = sum + y;
                    comp = (t - sum) - y;
                    sum = t;
                }
            }
            double dd = (double)sum + (double)comp;
            dv[s] = (float)dd;
            iv[s] = idx;
        } else {
            dv[s] = CUDART_INF_F;
            iv[s] = 0x7FFFFFFF;
        }
    }

    float wsum = 0.f, wvsum = 0.f;
    for (int it = 0; it < TOPK; it++) {
        float bv = CUDART_INF_F; int bidx = 0x7FFFFFFF; int bs = 0;
        #pragma unroll
        for (int s = 0; s < NSLOT; s++) {
            if (dv[s] < bv || (dv[s] == bv && iv[s] < bidx)) {
                bv = dv[s]; bidx = iv[s]; bs = s;
            }
        }
        float v = bv; int vidx = bidx; int l = lane;
        #pragma unroll
        for (int o = 16; o; o >>= 1) {
            float ov = __shfl_xor_sync(~0u, v, o);
            int   oi = __shfl_xor_sync(~0u, vidx, o);
            int   ol = __shfl_xor_sync(~0u, l, o);
            if (ov < v || (ov == v && oi < vidx)) { v = ov; vidx = oi; l = ol; }
        }
        if (lane == l) { dv[bs] = CUDART_INF_F; iv[bs] = 0x7FFFFFFF; }
        float w = 1.f / (v + DIST_EPS);
        wsum += w;
        wvsum += w * memv[vidx];
    }
    if (lane == 0)
        out[row] = 0.9f * (wvsum / wsum) + 0.1f * g_net[row];
}

// ---------------- launch ----------------
extern "C" void kernel_launch(void* const* d_in, const int* in_sizes, int n_in,
                              void* d_out, int out_size) {
    const float* states = (const float*)d_in[0];
    const float* W1 = (const float*)d_in[1];
    const float* b1 = (const float*)d_in[2];
    const float* W2 = (const float*)d_in[3];
    const float* b2 = (const float*)d_in[4];
    const float* ln_g = (const float*)d_in[5];
    const float* ln_b = (const float*)d_in[6];
    const float* keys = (const float*)d_in[7];
    const float* memv = (const float*)d_in[8];
    const float* V1 = (const float*)d_in[9];
    const float* c1 = (const float*)d_in[10];
    const float* V2 = (const float*)d_in[11];
    const float* c2 = (const float*)d_in[12];
    const float* V3 = (const float*)d_in[13];
    const float* c3 = (const float*)d_in[14];
    float* out = (float*)d_out;

    cudaFuncSetAttribute(dist_topk_kernel,
                         cudaFuncAttributeMaxDynamicSharedMemorySize,
                         (int)sizeof(DSmem));

    k2_kernel<<<(M_KEYS + 7) / 8, 256>>>(keys);
    dim3 g1(B_ROWS / 64, (H_DIM * 2) / 64);
    enc1_kernel<<<g1, 256>>>(states, W1, b1, V1, c1);
    enc2_kernel<<<B_ROWS / 8, 128>>>(W2, b2, ln_g, ln_b, V2, c2, V3, c3);
    dim3 g3(B_ROWS / RB, NSPLIT);
    dist_topk_kernel<<<g3, 256, sizeof(DSmem)>>>(keys);
    final_kernel<<<B_ROWS / 4, 128>>>(keys, memv, out);
}

// round 15
// speedup vs baseline: 1.2922x; 1.0196x over previous
#include <cuda_runtime.h>
#include <math_constants.h>
#include <cstdint>

// ---------------- problem constants ----------------
#define B_ROWS 4096
#define S_DIM  544
#define H_DIM  256
#define D_DIM  128
#define M_KEYS 50000
#define TOPK   50
#define NSPLIT 8
#define CHUNK  (M_KEYS / NSPLIT)   // 6250
#define RB     64                  // rows per CTA in dist kernel
#define KT     256                 // keys per tile
#define DKS    32                  // d-slice for key staging
#define NSLICE (D_DIM / DKS)       // 4
#define CB     32                  // candidate buffer per row
#define LN_EPS   1e-5f
#define DIST_EPS 1e-7f

// ---------------- scratch (device globals; no allocs allowed) ----------------
__device__ float g_h  [B_ROWS * H_DIM];
__device__ float g_v1 [B_ROWS * H_DIM];
__device__ float g_q  [B_ROWS * D_DIM];
__device__ float g_q2 [B_ROWS];
__device__ float g_net[B_ROWS];
__device__ float g_k2 [M_KEYS];
__device__ float g_cd [B_ROWS * NSPLIT * TOPK];
__device__ int   g_ci [B_ROWS * NSPLIT * TOPK];

// ---------------- f32x2 packed helpers (Blackwell) ----------------
__device__ __forceinline__ unsigned long long pack_dup(float x) {
    unsigned long long r;
    asm("mov.b64 %0, {%1, %1};" : "=l"(r) : "f"(x));
    return r;
}
__device__ __forceinline__ float2 unpack_f2(unsigned long long v) {
    float2 r;
    asm("mov.b64 {%0, %1}, %2;" : "=f"(r.x), "=f"(r.y) : "l"(v));
    return r;
}
__device__ __forceinline__ void ffma2(unsigned long long& d,
                                      unsigned long long a,
                                      unsigned long long b) {
    asm("fma.rn.f32x2 %0, %1, %2, %0;" : "+l"(d) : "l"(a), "l"(b));
}
__device__ __forceinline__ void cp_async16(unsigned int smem_dst, const void* gmem_src) {
    asm volatile("cp.async.cg.shared.global [%0], [%1], 16;"
                 :: "r"(smem_dst), "l"(gmem_src));
}
__device__ __forceinline__ void cp_async_commit() {
    asm volatile("cp.async.commit_group;");
}
template <int N>
__device__ __forceinline__ void cp_async_wait() {
    asm volatile("cp.async.wait_group %0;" :: "n"(N));
}

// ---------------- kernel 1: ||k||^2 ----------------
__global__ void k2_kernel(const float* __restrict__ keys) {
    int warp = (blockIdx.x * blockDim.x + threadIdx.x) >> 5;
    int lane = threadIdx.x & 31;
    if (warp >= M_KEYS) return;
    float4 v = *reinterpret_cast<const float4*>(&keys[warp * D_DIM + lane * 4]);
    float s = v.x * v.x + v.y * v.y + v.z * v.z + v.w * v.w;
    #pragma unroll
    for (int o = 16; o; o >>= 1) s += __shfl_xor_sync(~0u, s, o);
    if (lane == 0) g_k2[warp] = s;
}

// ---------------- kernel 2: h = relu(X@W1+b1), v1 = relu(X@V1+c1) ----------------
__global__ __launch_bounds__(256) void enc1_kernel(
    const float* __restrict__ X,
    const float* __restrict__ W1, const float* __restrict__ b1,
    const float* __restrict__ V1, const float* __restrict__ c1) {
    __shared__ float Xs[8][68];
    __shared__ float Ws[8][68];
    int i0 = blockIdx.x * 64;
    int j0 = blockIdx.y * 64;
    int tid = threadIdx.x;
    int ty = tid >> 4, tx = tid & 15;
    unsigned long long acc[4][2];
    #pragma unroll
    for (int a = 0; a < 4; a++) { acc[a][0] = 0ull; acc[a][1] = 0ull; }

    for (int k0 = 0; k0 < S_DIM; k0 += 8) {
        {
            #pragma unroll
            for (int p = 0; p < 2; p++) {
                int e = tid + p * 256;
                int d = e & 7, i = e >> 3;
                Xs[d][i] = X[(i0 + i) * S_DIM + k0 + d];
            }
        }
        {
            #pragma unroll
            for (int p = 0; p < 2; p++) {
                int e = tid + p * 256;
                int j = e & 63, d = e >> 6;
                int jj = j0 + j;
                float w = (jj < H_DIM) ? W1[(k0 + d) * H_DIM + jj]
                                       : V1[(k0 + d) * H_DIM + (jj - H_DIM)];
                Ws[d][j] = w;
            }
        }
        __syncthreads();
        #pragma unroll
        for (int d = 0; d < 8; d++) {
            float4 xv = *reinterpret_cast<const float4*>(&Xs[d][ty * 4]);
            ulonglong2 wp = *reinterpret_cast<const ulonglong2*>(&Ws[d][tx * 4]);
            unsigned long long x0 = pack_dup(xv.x);
            unsigned long long x1 = pack_dup(xv.y);
            unsigned long long x2 = pack_dup(xv.z);
            unsigned long long x3 = pack_dup(xv.w);
            ffma2(acc[0][0], wp.x, x0); ffma2(acc[0][1], wp.y, x0);
            ffma2(acc[1][0], wp.x, x1); ffma2(acc[1][1], wp.y, x1);
            ffma2(acc[2][0], wp.x, x2); ffma2(acc[2][1], wp.y, x2);
            ffma2(acc[3][0], wp.x, x3); ffma2(acc[3][1], wp.y, x3);
        }
        __syncthreads();
    }
    #pragma unroll
    for (int a = 0; a < 4; a++) {
        int i = i0 + ty * 4 + a;
        float cv[4];
        {
            float2 p0 = unpack_f2(acc[a][0]);
            float2 p1 = unpack_f2(acc[a][1]);
            cv[0] = p0.x; cv[1] = p0.y; cv[2] = p1.x; cv[3] = p1.y;
        }
        #pragma unroll
        for (int b = 0; b < 4; b++) {
            int jj = j0 + tx * 4 + b;
            float bias = (jj < H_DIM) ? b1[jj] : c1[jj - H_DIM];
            float v = fmaxf(cv[b] + bias, 0.f);
            if (jj < H_DIM) g_h [i * H_DIM + jj]         = v;
            else            g_v1[i * H_DIM + jj - H_DIM] = v;
        }
    }
}

// ---------------- kernel 3: q = LN(h@W2+b2); v2 = relu(v1@V2+c2); net = v2@V3+c3 ----------------
__device__ __forceinline__ float block_sum_128(float v, float* sred, int tid) {
    #pragma unroll
    for (int o = 16; o; o >>= 1) v += __shfl_xor_sync(~0u, v, o);
    __syncthreads();
    if ((tid & 31) == 0) sred[tid >> 5] = v;
    __syncthreads();
    return sred[0] + sred[1] + sred[2] + sred[3];
}

__global__ __launch_bounds__(128) void enc2_kernel(
    const float* __restrict__ W2, const float* __restrict__ b2,
    const float* __restrict__ ln_g, const float* __restrict__ ln_b,
    const float* __restrict__ V2, const float* __restrict__ c2,
    const float* __restrict__ V3, const float* __restrict__ c3) {
    __shared__ float hs[8][H_DIM];
    __shared__ float vs[8][H_DIM];
    __shared__ float sred[4];
    int r0 = blockIdx.x * 8;
    int tid = threadIdx.x;   // 0..127 = output dim

    for (int e = tid; e < 8 * H_DIM / 4; e += 128) {
        int r = e >> 6;
        int c = (e & 63) * 4;
        *reinterpret_cast<float4*>(&hs[r][c]) =
            *reinterpret_cast<const float4*>(&g_h[(r0 + r) * H_DIM + c]);
        *reinterpret_cast<float4*>(&vs[r][c]) =
            *reinterpret_cast<const float4*>(&g_v1[(r0 + r) * H_DIM + c]);
    }
    __syncthreads();

    float accq[8], accv[8];
    float bq = b2[tid], bv = c2[tid];
    #pragma unroll
    for (int r = 0; r < 8; r++) { accq[r] = bq; accv[r] = bv; }

    for (int k = 0; k < H_DIM; k++) {
        float w2  = W2[k * D_DIM + tid];
        float v2w = V2[k * D_DIM + tid];
        #pragma unroll
        for (int r = 0; r < 8; r++) {
            accq[r] += hs[r][k] * w2;
            accv[r] += vs[r][k] * v2w;
        }
    }

    float g = ln_g[tid], bb = ln_b[tid], v3 = V3[tid], c3v = c3[0];
    for (int r = 0; r < 8; r++) {
        float x = accq[r];
        float mu = block_sum_128(x, sred, tid) * (1.f / 128.f);
        float dif = x - mu;
        float var = block_sum_128(dif * dif, sred, tid) * (1.f / 128.f);
        float qn = dif * rsqrtf(var + LN_EPS) * g + bb;
        g_q[(r0 + r) * D_DIM + tid] = qn;
        float q2 = block_sum_128(qn * qn, sred, tid);
        if (tid == 0) g_q2[r0 + r] = q2;
        float vv = fmaxf(accv[r], 0.f);
        float nv = block_sum_128(vv * v3, sred, tid);
        if (tid == 0) g_net[r0 + r] = nv + c3v;
    }
}

// ---------------- kernel 4: fused distance GEMM + per-chunk top-50 ----------------
// Tile: 64 rows x 256 keys. Warp w: rows (w>>1)*16..+15, keys (w&1)*128..+127.
// Lane owns keys {kh*128 + kk*32 + lane}. acc[rp][kk] packs rows (2rp,2rp+1).
// Key smem row-major XOR-swizzled ks[m][d ^ ((m&7)<<2)], staged via cp.async.
struct __align__(16) DSmem {
    float qs[D_DIM][RB];         // q tile transposed, 256B rows (no pad needed:
                                 // compute loads are warp-uniform broadcasts)
    float ks[KT][DKS];           // swizzled key slice (128B rows), single buffer
    float k2s[KT];
    float q2s[RB];
    float thr[RB];
    int   cnt[RB];
    int   tcnt[RB];
    float tmax[RB];
    int   tmaxp[RB];
    float cdv[RB][CB];
    int   civ[RB][CB];
    float td[RB][TOPK];
    int   ti[RB][TOPK];
    int   s_overflow;
};

__device__ __forceinline__ void recompute_max(DSmem& sm, int lr, int lane) {
    float v = sm.td[lr][lane];
    int p = lane;
    if (lane < TOPK - 32) {
        float v2 = sm.td[lr][lane + 32];
        if (v2 > v) { v = v2; p = lane + 32; }
    }
    #pragma unroll
    for (int o = 16; o; o >>= 1) {
        float ov = __shfl_xor_sync(~0u, v, o);
        int   op = __shfl_xor_sync(~0u, p, o);
        if (ov > v) { v = ov; p = op; }
    }
    if (lane == 0) { sm.tmax[lr] = v; sm.tmaxp[lr] = p; }
    __syncwarp();
}

__global__ __launch_bounds__(256, 2) void dist_topk_kernel(const float* __restrict__ keys) {
    extern __shared__ char smem_raw[];
    DSmem& sm = *reinterpret_cast<DSmem*>(smem_raw);
    int tid = threadIdx.x;
    int r0 = blockIdx.x * RB;
    int split = blockIdx.y;
    int cstart = split * CHUNK;
    int cend = cstart + CHUNK;
    int lane = tid & 31, warp = tid >> 5;
    int wg = warp >> 1;          // row group 0..3 -> rows wg*16..+15
    int kh = warp & 1;           // key half 0..1 -> keys kh*128..+127

    for (int r = tid; r < RB; r += 256) {
        sm.q2s[r] = g_q2[r0 + r];
        sm.thr[r] = CUDART_INF_F;
        sm.cnt[r] = 0;
        sm.tcnt[r] = 0;
        sm.tmax[r] = -CUDART_INF_F;
        sm.tmaxp[r] = 0;
    }
    // stage the full q tile [64 rows x 128 d] once (transposed: qs[d][row])
    for (int e = tid; e < RB * (D_DIM / 4); e += 256) {
        int r = e >> 5;              // 0..63
        int dp = (e & 31) * 4;       // 0..124 step 4
        float4 v = *reinterpret_cast<const float4*>(&g_q[(r0 + r) * D_DIM + dp]);
        sm.qs[dp + 0][r] = v.x; sm.qs[dp + 1][r] = v.y;
        sm.qs[dp + 2][r] = v.z; sm.qs[dp + 3][r] = v.w;
    }
    __syncthreads();

    for (int m0 = cstart; m0 < cend; m0 += KT) {
        sm.k2s[tid] = g_k2[min(m0 + tid, M_KEYS - 1)];

        unsigned long long acc[8][4];   // [rowpair rp 0..7][key kk 0..3]
        #pragma unroll
        for (int a = 0; a < 8; a++)
            #pragma unroll
            for (int b = 0; b < 4; b++) acc[a][b] = 0ull;

        int csw = (lane & 7) << 2;   // compute-side swizzle offset

        #pragma unroll 1
        for (int s = 0; s < NSLICE; s++) {
            int d0 = s * DKS;
            // stage slice s (256 keys x 32 dims): 8 x cp.async16 per thread
            #pragma unroll
            for (int p = 0; p < 8; p++) {
                int e = tid + p * 256;          // 0..2047
                int m = e >> 3;                 // key 0..255
                int dp = (e & 7) * 4;           // d-offset 0..28
                int c = dp ^ ((m & 7) << 2);
                int mg = min(m0 + m, M_KEYS - 1);
                cp_async16(
                    (unsigned int)__cvta_generic_to_shared(&sm.ks[m][c]),
                    &keys[mg * D_DIM + d0 + dp]);
            }
            cp_async_commit();
            cp_async_wait<0>();
            __syncthreads();

            #pragma unroll
            for (int dc = 0; dc < DKS; dc += 4) {
                float4 kv[4];
                #pragma unroll
                for (int kk = 0; kk < 4; kk++) {
                    kv[kk] = *reinterpret_cast<const float4*>(
                        &sm.ks[kh * 128 + kk * 32 + lane][dc ^ csw]);
                }
                #pragma unroll
                for (int dd = 0; dd < 4; dd++) {
                    int d = d0 + dc + dd;
                    ulonglong2 qA = *reinterpret_cast<const ulonglong2*>(
                        &sm.qs[d][wg * 16]);
                    ulonglong2 qB = *reinterpret_cast<const ulonglong2*>(
                        &sm.qs[d][wg * 16 + 8]);
                    unsigned long long k0 = pack_dup(reinterpret_cast<const float*>(&kv[0])[dd]);
                    unsigned long long k1 = pack_dup(reinterpret_cast<const float*>(&kv[1])[dd]);
                    unsigned long long k2 = pack_dup(reinterpret_cast<const float*>(&kv[2])[dd]);
                    unsigned long long k3 = pack_dup(reinterpret_cast<const float*>(&kv[3])[dd]);
                    ffma2(acc[0][0], qA.x, k0); ffma2(acc[0][1], qA.x, k1);
                    ffma2(acc[0][2], qA.x, k2); ffma2(acc[0][3], qA.x, k3);
                    ffma2(acc[1][0], qA.y, k0); ffma2(acc[1][1], qA.y, k1);
                    ffma2(acc[1][2], qA.y, k2); ffma2(acc[1][3], qA.y, k3);
                    ffma2(acc[2][0], qB.x, k0); ffma2(acc[2][1], qB.x, k1);
                    ffma2(acc[2][2], qB.x, k2); ffma2(acc[2][3], qB.x, k3);
                    ffma2(acc[3][0], qB.y, k0); ffma2(acc[3][1], qB.y, k1);
                    ffma2(acc[3][2], qB.y, k2); ffma2(acc[3][3], qB.y, k3);
                    ulonglong2 qC = *reinterpret_cast<const ulonglong2*>(
                        &sm.qs[d][wg * 16 + 4]);
                    ulonglong2 qD = *reinterpret_cast<const ulonglong2*>(
                        &sm.qs[d][wg * 16 + 12]);
                    ffma2(acc[4][0], qC.x, k0); ffma2(acc[4][1], qC.x, k1);
                    ffma2(acc[4][2], qC.x, k2); ffma2(acc[4][3], qC.x, k3);
                    ffma2(acc[5][0], qC.y, k0); ffma2(acc[5][1], qC.y, k1);
                    ffma2(acc[5][2], qC.y, k2); ffma2(acc[5][3], qC.y, k3);
                    ffma2(acc[6][0], qD.x, k0); ffma2(acc[6][1], qD.x, k1);
                    ffma2(acc[6][2], qD.x, k2); ffma2(acc[6][3], qD.x, k3);
                    ffma2(acc[7][0], qD.y, k0); ffma2(acc[7][1], qD.y, k1);
                    ffma2(acc[7][2], qD.y, k2); ffma2(acc[7][3], qD.y, k3);
                }
            }
            __syncthreads();   // protect single ks buffer before next slice
        }
        // acc row mapping: rp 0..3 -> rows wg*16 + {0,1,2,3} (pairs 0-1, 2-3)?
        // careful: qA pairs rows (0,1),(2,3)? qA = rows wg*16..+3 -> acc[0]=rows(+0,+1), acc[1]=rows(+2,+3)
        // qC = rows +4..+7 -> acc[4]=(+4,+5), acc[5]=(+6,+7)
        // qB = rows +8..+11 -> acc[2]=(+8,+9), acc[3]=(+10,+11)
        // qD = rows +12..+15 -> acc[6]=(+12,+13), acc[7]=(+14,+15)
        const int rp_rowbase[8] = {0, 2, 8, 10, 4, 6, 12, 14};

        // ---- threshold-filtered push + exact merge (retry on overflow) ----
        unsigned long long done = 0;
        #pragma unroll
        for (int kk = 0; kk < 4; kk++)
            if (m0 + kh * 128 + kk * 32 + lane >= cend)
                done |= (0x1111111111111111ULL << kk);

        while (true) {
            if (tid == 0) sm.s_overflow = 0;
            __syncthreads();
            #pragma unroll
            for (int rp = 0; rp < 8; rp++) {
                #pragma unroll
                for (int h = 0; h < 2; h++) {
                    int rl = rp_rowbase[rp] + h;          // row-local 0..15
                    int lr = wg * 16 + rl;
                    float q2v = sm.q2s[lr];
                    float t = sm.thr[lr];
                    #pragma unroll
                    for (int kk = 0; kk < 4; kk++) {
                        int v = (rp * 2 + h) * 4 + kk;    // unique bit per (rp,h,kk)
                        if (done & (1ULL << v)) continue;
                        float2 dots = unpack_f2(acc[rp][kk]);
                        float dot = h ? dots.y : dots.x;
                        int lm = kh * 128 + kk * 32 + lane;
                        float dist = q2v + sm.k2s[lm] - 2.f * dot;
                        if (dist < t) {
                            int p = atomicAdd(&sm.cnt[lr], 1);
                            if (p < CB) {
                                sm.cdv[lr][p] = dist;
                                sm.civ[lr][p] = m0 + lm;
                                done |= (1ULL << v);
                            } else {
                                sm.s_overflow = 1;
                            }
                        } else {
                            done |= (1ULL << v);   // thr only decreases: safe to retire
                        }
                    }
                }
            }
            __syncthreads();
            // merge: warp w owns rows [w*8, w*8+8)
            for (int rr = 0; rr < 8; rr++) {
                int lr = warp * 8 + rr;
                int c = min(sm.cnt[lr], CB);
                for (int k = 0; k < c; k++) {
                    float dv = sm.cdv[lr][k];
                    int iv = sm.civ[lr][k];
                    int tc_ = sm.tcnt[lr];
                    if (tc_ < TOPK) {
                        if (lane == 0) {
                            sm.td[lr][tc_] = dv; sm.ti[lr][tc_] = iv;
                            sm.tcnt[lr] = tc_ + 1;
                        }
                        __syncwarp();
                        if (tc_ + 1 == TOPK) recompute_max(sm, lr, lane);
                    } else if (dv < sm.tmax[lr]) {
                        if (lane == 0) {
                            int mp = sm.tmaxp[lr];
                            sm.td[lr][mp] = dv; sm.ti[lr][mp] = iv;
                        }
                        __syncwarp();
                        recompute_max(sm, lr, lane);
                    }
                }
                if (lane == 0) {
                    sm.cnt[lr] = 0;
                    sm.thr[lr] = (sm.tcnt[lr] == TOPK) ? sm.tmax[lr] : CUDART_INF_F;
                }
            }
            __syncthreads();
            int of = sm.s_overflow;
            __syncthreads();
            if (!of) break;
        }
    }

    // write per-chunk top-50 indices (unsorted)
    for (int rr = 0; rr < 8; rr++) {
        int lr = warp * 8 + rr;
        int gr = r0 + lr;
        for (int e = lane; e < TOPK; e += 32) {
            g_cd[(gr * NSPLIT + split) * TOPK + e] = sm.td[lr][e];
            g_ci[(gr * NSPLIT + split) * TOPK + e] = sm.ti[lr][e];
        }
    }
}

// ---------------- kernel 5: EXACT rescore of NSPLIT x 50 candidates -> top-50 -> output ----------------
#define NC      (NSPLIT * TOPK)          // 400
#define NSLOT   ((NC + 31) / 32)         // 13

__global__ __launch_bounds__(128) void final_kernel(const float* __restrict__ keys,
                                                    const float* __restrict__ memv,
                                                    float* __restrict__ out) {
    __shared__ float qsh[4][D_DIM];
    int warp = threadIdx.x >> 5, lane = threadIdx.x & 31;
    int row = blockIdx.x * 4 + warp;
    const int* ci = &g_ci[row * NC];

    for (int i = lane; i < D_DIM / 4; i += 32)
        reinterpret_cast<float4*>(qsh[warp])[i] =
            reinterpret_cast<const float4*>(&g_q[row * D_DIM])[i];
    __syncwarp();

    float dv[NSLOT]; int iv[NSLOT];
    #pragma unroll 1
    for (int s = 0; s < NSLOT; s++) {
        int e = lane + s * 32;
        if (e < NC) {
            int idx = ci[e];
            const float4* kp = reinterpret_cast<const float4*>(&keys[idx * D_DIM]);
            const float4* qp = reinterpret_cast<const float4*>(qsh[warp]);
            float sum = 0.f, comp = 0.f;
            #pragma unroll 8
            for (int i = 0; i < D_DIM / 4; i++) {
                float4 kv = kp[i];
                float4 qv = qp[i];
                float df[4] = {qv.x - kv.x, qv.y - kv.y, qv.z - kv.z, qv.w - kv.w};
                #pragma unroll
                for (int j = 0; j < 4; j++) {
                    float p = df[j] * df[j];
                    float y = p - comp;
                    float t = sum + y;
                    comp = (t - sum) - y;
                    sum = t;
                }
            }
            double dd = (double)sum + (double)comp;
            dv[s] = (float)dd;
            iv[s] = idx;
        } else {
            dv[s] = CUDART_INF_F;
            iv[s] = 0x7FFFFFFF;
        }
    }

    float wsum = 0.f, wvsum = 0.f;
    for (int it = 0; it < TOPK; it++) {
        float bv = CUDART_INF_F; int bidx = 0x7FFFFFFF; int bs = 0;
        #pragma unroll
        for (int s = 0; s < NSLOT; s++) {
            if (dv[s] < bv || (dv[s] == bv && iv[s] < bidx)) {
                bv = dv[s]; bidx = iv[s]; bs = s;
            }
        }
        float v = bv; int vidx = bidx; int l = lane;
        #pragma unroll
        for (int o = 16; o; o >>= 1) {
            float ov = __shfl_xor_sync(~0u, v, o);
            int   oi = __shfl_xor_sync(~0u, vidx, o);
            int   ol = __shfl_xor_sync(~0u, l, o);
            if (ov < v || (ov == v && oi < vidx)) { v = ov; vidx = oi; l = ol; }
        }
        if (lane == l) { dv[bs] = CUDART_INF_F; iv[bs] = 0x7FFFFFFF; }
        float w = 1.f / (v + DIST_EPS);
        wsum += w;
        wvsum += w * memv[vidx];
    }
    if (lane == 0)
        out[row] = 0.9f * (wvsum / wsum) + 0.1f * g_net[row];
}

// ---------------- launch ----------------
extern "C" void kernel_launch(void* const* d_in, const int* in_sizes, int n_in,
                              void* d_out, int out_size) {
    const float* states = (const float*)d_in[0];
    const float* W1 = (const float*)d_in[1];
    const float* b1 = (const float*)d_in[2];
    const float* W2 = (const float*)d_in[3];
    const float* b2 = (const float*)d_in[4];
    const float* ln_g = (const float*)d_in[5];
    const float* ln_b = (const float*)d_in[6];
    const float* keys = (const float*)d_in[7];
    const float* memv = (const float*)d_in[8];
    const float* V1 = (const float*)d_in[9];
    const float* c1 = (const float*)d_in[10];
    const float* V2 = (const float*)d_in[11];
    const float* c2 = (const float*)d_in[12];
    const float* V3 = (const float*)d_in[13];
    const float* c3 = (const float*)d_in[14];
    float* out = (float*)d_out;

    cudaFuncSetAttribute(dist_topk_kernel,
                         cudaFuncAttributeMaxDynamicSharedMemorySize,
                         (int)sizeof(DSmem));

    k2_kernel<<<(M_KEYS + 7) / 8, 256>>>(keys);
    dim3 g1(B_ROWS / 64, (H_DIM * 2) / 64);
    enc1_kernel<<<g1, 256>>>(states, W1, b1, V1, c1);
    enc2_kernel<<<B_ROWS / 8, 128>>>(W2, b2, ln_g, ln_b, V2, c2, V3, c3);
    dim3 g3(B_ROWS / RB, NSPLIT);
    dist_topk_kernel<<<g3, 256, sizeof(DSmem)>>>(keys);
    final_kernel<<<B_ROWS / 4, 128>>>(keys, memv, out);
}